// round 1
// baseline (speedup 1.0000x reference)
#include <cuda_runtime.h>
#include <stdint.h>

// Problem constants
#define BB 2
#define NN 16384
#define KK 32
#define FF 64
#define EE 16
#define NT (BB * NN)      // 32768 nodes total
#define SK (FF * EE)      // 1024 = contraction length for stage 2

// Scratch (static __device__ arrays — no runtime allocation)
__device__ float g_S[(size_t)NT * SK];   // 128 MB: per-node S[l][n] (mean folded in)
__device__ float g_W2[SK * FF];          // 256 KB: W2[k][m] = w[l][m][n], k = l*16+n

// ---- packed f32x2 helpers (FFMA2 path; 2x fp32 FMA throughput) ----
static __device__ __forceinline__ unsigned long long pk2(float x, float y) {
    unsigned long long r;
    asm("mov.b64 %0, {%1, %2};" : "=l"(r) : "f"(x), "f"(y));
    return r;
}
static __device__ __forceinline__ void upk2(unsigned long long v, float &x, float &y) {
    asm("mov.b64 {%0, %1}, %2;" : "=f"(x), "=f"(y) : "l"(v));
}
static __device__ __forceinline__ unsigned long long ffma2(
    unsigned long long a, unsigned long long b, unsigned long long c) {
    unsigned long long d;
    asm("fma.rn.f32x2 %0, %1, %2, %3;" : "=l"(d) : "l"(a), "l"(b), "l"(c));
    return d;
}

// ---- kernel 0: transpose w[l][m][n] -> W2[(l*16+n)][m] (tiny, 64K elems) ----
__global__ void k_w2(const float* __restrict__ w) {
    int id = blockIdx.x * blockDim.x + threadIdx.x;   // id = k*64 + m
    if (id < SK * FF) {
        int m = id & (FF - 1);
        int k = id >> 6;
        int l = k >> 4;
        int n = k & 15;
        g_W2[id] = w[l * (FF * EE) + m * EE + n];
    }
}

// ---- kernel 1: per-node S[l][n] = (1/K) * sum_j sliced[j][l] * edges[j][n] ----
// 2 warps per node (lane owns one l row of S, 16 n-accumulators as 8 f32x2).
// 4 nodes per 256-thread block.
__global__ __launch_bounds__(256) void k_stage1(
    const float* __restrict__ nodes,
    const int*   __restrict__ nlist,
    const float* __restrict__ edges)
{
    __shared__ __align__(16) float s_e[4][KK * EE];   // 4 nodes x 512 floats = 8 KB
    const int t    = threadIdx.x;
    const int warp = t >> 5;
    const int lane = t & 31;
    const int nl   = warp >> 1;          // node within block: 0..3
    const int half = warp & 1;           // which 32 l-rows this warp owns
    const int g    = blockIdx.x * 4 + nl;  // global node 0..32767
    const int b    = g >> 14;            // batch

    // Cooperative load of this node's edge tile (512 floats) into smem.
    {
        const float4* ep = reinterpret_cast<const float4*>(edges + (size_t)g * (KK * EE));
        float4* sp = reinterpret_cast<float4*>(s_e[nl]);
        int u = half * 32 + lane;        // 0..63
        sp[u]      = ep[u];
        sp[u + 64] = ep[u + 64];
    }
    // Each lane holds one neighbor index; broadcast by shuffle in the j-loop.
    const int my_idx = nlist[(size_t)g * KK + lane];
    __syncthreads();

    const int l = half * 32 + lane;      // l row this lane owns (0..63)
    const float* nb = nodes + (size_t)b * (NN * FF) + l;

    unsigned long long acc[8];
#pragma unroll
    for (int p = 0; p < 8; p++) acc[p] = 0ull;   // (0.0f, 0.0f)

#pragma unroll 8
    for (int j = 0; j < KK; j++) {
        int jdx = __shfl_sync(0xffffffffu, my_idx, j);
        float a = __ldg(nb + (size_t)jdx * FF);          // sliced[j][l], 128B/warp coalesced (L2 hit)
        unsigned long long a2 = pk2(a, a);
        const ulonglong2* e2 = reinterpret_cast<const ulonglong2*>(&s_e[nl][j * EE]);
#pragma unroll
        for (int q = 0; q < 4; q++) {                    // 4x LDS.128 broadcast -> 8 f32x2
            ulonglong2 ev = e2[q];
            acc[2 * q]     = ffma2(a2, ev.x, acc[2 * q]);
            acc[2 * q + 1] = ffma2(a2, ev.y, acc[2 * q + 1]);
        }
    }

    // Fold mean (1/K) and store 16 floats (4x STG.128).
    float* outp = g_S + (size_t)g * SK + l * EE;
    const float sc = 1.0f / (float)KK;
#pragma unroll
    for (int q = 0; q < 4; q++) {
        float x0, y0, x1, y1;
        upk2(acc[2 * q], x0, y0);
        upk2(acc[2 * q + 1], x1, y1);
        reinterpret_cast<float4*>(outp)[q] =
            make_float4(x0 * sc, y0 * sc, x1 * sc, y1 * sc);
    }
}

// ---- kernel 2: SGEMM out[32768 x 64] = g_S[32768 x 1024] @ g_W2[1024 x 64] ----
// Block tile: 128 (M) x 64 (N), K-step 16, 256 threads, per-thread 8x4 via f32x2
// row-pairing (no per-element dup: a2 comes straight from LDS.64 of As[k][row]).
__global__ __launch_bounds__(256) void k_stage2(float* __restrict__ out)
{
    __shared__ __align__(16) float As[16][132];  // [k][row], padded vs bank conflicts
    __shared__ __align__(16) float Ws[16][64];   // [k][m]

    const int t  = threadIdx.x;
    const int tx = t & 15;          // column group: 4 cols
    const int ty = t >> 4;          // row group: 8 rows
    const int m0 = blockIdx.x * 128;
    const int r0 = ty * 8;
    const int c0 = tx * 4;

    unsigned long long acc[4][4];
#pragma unroll
    for (int rp = 0; rp < 4; rp++)
#pragma unroll
        for (int c = 0; c < 4; c++) acc[rp][c] = 0ull;

    for (int kk = 0; kk < SK; kk += 16) {
        // Load S tile 128x16 (coalesced float4), store transposed into As[k][row].
#pragma unroll
        for (int q = 0; q < 2; q++) {
            int u  = t + q * 256;            // 0..511
            int r  = u >> 2;                 // 0..127
            int kq = u & 3;                  // 0..3 (float4 within the 16-k row)
            float4 v = *reinterpret_cast<const float4*>(
                g_S + (size_t)(m0 + r) * SK + kk + kq * 4);
            As[kq * 4 + 0][r] = v.x;
            As[kq * 4 + 1][r] = v.y;
            As[kq * 4 + 2][r] = v.z;
            As[kq * 4 + 3][r] = v.w;
        }
        // Load W2 tile 16x64 (coalesced float4).
        {
            int kr = t >> 4;                 // 0..15
            int mv = (t & 15) * 4;           // 0..60
            float4 v = *reinterpret_cast<const float4*>(
                g_W2 + (size_t)(kk + kr) * FF + mv);
            *reinterpret_cast<float4*>(&Ws[kr][mv]) = v;
        }
        __syncthreads();

#pragma unroll
        for (int k = 0; k < 16; k++) {
            float4 w4 = *reinterpret_cast<const float4*>(&Ws[k][c0]);
            unsigned long long wd[4] = {
                pk2(w4.x, w4.x), pk2(w4.y, w4.y), pk2(w4.z, w4.z), pk2(w4.w, w4.w)
            };
#pragma unroll
            for (int rp = 0; rp < 4; rp++) {
                unsigned long long a2 = *reinterpret_cast<const unsigned long long*>(
                    &As[k][r0 + rp * 2]);    // rows (2rp, 2rp+1) pair, LDS.64 broadcast
#pragma unroll
                for (int c = 0; c < 4; c++)
                    acc[rp][c] = ffma2(a2, wd[c], acc[rp][c]);
            }
        }
        __syncthreads();
    }

    // Store C: per thread 8 rows x 4 cols as float4 per row.
#pragma unroll
    for (int rp = 0; rp < 4; rp++) {
        float x[4], y[4];
#pragma unroll
        for (int c = 0; c < 4; c++) upk2(acc[rp][c], x[c], y[c]);
        int row = m0 + r0 + rp * 2;
        *reinterpret_cast<float4*>(out + (size_t)row * FF + c0) =
            make_float4(x[0], x[1], x[2], x[3]);
        *reinterpret_cast<float4*>(out + (size_t)(row + 1) * FF + c0) =
            make_float4(y[0], y[1], y[2], y[3]);
    }
}

extern "C" void kernel_launch(void* const* d_in, const int* in_sizes, int n_in,
                              void* d_out, int out_size) {
    const float* nodes = (const float*)d_in[0];
    const int*   nlist = (const int*)d_in[1];
    const float* edges = (const float*)d_in[2];
    const float* w     = (const float*)d_in[3];
    float* out = (float*)d_out;
    (void)in_sizes; (void)n_in; (void)out_size;

    k_w2<<<(SK * FF + 255) / 256, 256>>>(w);
    k_stage1<<<NT / 4, 256>>>(nodes, nlist, edges);
    k_stage2<<<NT / 128, 256>>>(out);
}

// round 3
// speedup vs baseline: 1.5526x; 1.5526x over previous
#include <cuda_runtime.h>
#include <cuda_bf16.h>
#include <stdint.h>

// Problem constants
#define BB 2
#define NN 16384
#define KK 32
#define FF 64
#define EE 16
#define NT (BB * NN)      // 32768 nodes
#define SK (FF * EE)      // 1024 = GEMM contraction length

// Scratch (static __device__ arrays — no runtime allocation)
__device__ __align__(16) __nv_bfloat16 g_Sh[(size_t)NT * SK];  // 64 MB: S hi
__device__ __align__(16) __nv_bfloat16 g_Sl[(size_t)NT * SK];  // 64 MB: S lo (residual)
__device__ __align__(16) __nv_bfloat16 g_Bh[FF * SK];          // B[n][k] = w2^T hi
__device__ __align__(16) __nv_bfloat16 g_Bl[FF * SK];          // B[n][k] lo

// ---- packed f32x2 helpers (stage1) ----
static __device__ __forceinline__ unsigned long long pk2(float x, float y) {
    unsigned long long r;
    asm("mov.b64 %0, {%1, %2};" : "=l"(r) : "f"(x), "f"(y));
    return r;
}
static __device__ __forceinline__ void upk2(unsigned long long v, float &x, float &y) {
    asm("mov.b64 {%0, %1}, %2;" : "=f"(x), "=f"(y) : "l"(v));
}
static __device__ __forceinline__ unsigned long long ffma2(
    unsigned long long a, unsigned long long b, unsigned long long c) {
    unsigned long long d;
    asm("fma.rn.f32x2 %0, %1, %2, %3;" : "=l"(d) : "l"(a), "l"(b), "l"(c));
    return d;
}
// cvt two f32 -> packed bf16x2 (hi_src in upper half, lo_src in lower half)
static __device__ __forceinline__ uint32_t bfpack(float hi, float lo) {
    uint32_t r;
    asm("cvt.rn.bf16x2.f32 %0, %1, %2;" : "=r"(r) : "f"(hi), "f"(lo));
    return r;
}

// ---- mma / ldmatrix helpers (arch-portable HMMA path; tcgen05 is not
//      available through this harness's compute_103 PTX target) ----
static __device__ __forceinline__ uint32_t smem_u32(const void* p) {
    uint32_t a;
    asm("{ .reg .u64 t; cvta.to.shared.u64 t, %1; cvt.u32.u64 %0, t; }" : "=r"(a) : "l"(p));
    return a;
}
static __device__ __forceinline__ void ldsm4(uint32_t* r, uint32_t addr) {
    asm volatile("ldmatrix.sync.aligned.m8n8.x4.shared.b16 {%0,%1,%2,%3}, [%4];"
                 : "=r"(r[0]), "=r"(r[1]), "=r"(r[2]), "=r"(r[3]) : "r"(addr));
}
static __device__ __forceinline__ void mma16816(float* c, const uint32_t* a,
                                                const uint32_t* b) {
    asm volatile(
        "mma.sync.aligned.m16n8k16.row.col.f32.bf16.bf16.f32 "
        "{%0,%1,%2,%3}, {%4,%5,%6,%7}, {%8,%9}, {%0,%1,%2,%3};"
        : "+f"(c[0]), "+f"(c[1]), "+f"(c[2]), "+f"(c[3])
        : "r"(a[0]), "r"(a[1]), "r"(a[2]), "r"(a[3]), "r"(b[0]), "r"(b[1]));
}

// ---- kernel 0: W split/transpose: g_Bh/g_Bl[n][k] = split(w[l][n][e]), k=l*16+e ----
__global__ void k_w2(const float* __restrict__ w) {
    int id = blockIdx.x * blockDim.x + threadIdx.x;   // id = n*1024 + k
    if (id < FF * SK) {
        int n = id >> 10;
        int k = id & 1023;
        int l = k >> 4;
        int e = k & 15;
        float v = w[l * (FF * EE) + n * EE + e];
        __nv_bfloat16 h = __float2bfloat16(v);
        g_Bh[id] = h;
        g_Bl[id] = __float2bfloat16(v - __bfloat162float(h));
    }
}

// ---- kernel 1: per-node S[l][n] = (1/K) * sum_j sliced[j][l] * edges[j][n],
//      written as split bf16 hi/lo, k-major (k = l*16 + n) ----
__global__ __launch_bounds__(256) void k_stage1(
    const float* __restrict__ nodes,
    const int*   __restrict__ nlist,
    const float* __restrict__ edges)
{
    __shared__ __align__(16) float s_e[4][KK * EE];
    const int t    = threadIdx.x;
    const int warp = t >> 5;
    const int lane = t & 31;
    const int nl   = warp >> 1;
    const int half = warp & 1;
    const int g    = blockIdx.x * 4 + nl;
    const int b    = g >> 14;

    {
        const float4* ep = reinterpret_cast<const float4*>(edges + (size_t)g * (KK * EE));
        float4* sp = reinterpret_cast<float4*>(s_e[nl]);
        int u = half * 32 + lane;
        sp[u]      = ep[u];
        sp[u + 64] = ep[u + 64];
    }
    const int my_idx = nlist[(size_t)g * KK + lane];
    __syncthreads();

    const int l = half * 32 + lane;
    const float* nb = nodes + (size_t)b * (NN * FF) + l;

    unsigned long long acc[8];
#pragma unroll
    for (int p = 0; p < 8; p++) acc[p] = 0ull;

#pragma unroll 8
    for (int j = 0; j < KK; j++) {
        int jdx = __shfl_sync(0xffffffffu, my_idx, j);
        float a = __ldg(nb + (size_t)jdx * FF);
        unsigned long long a2 = pk2(a, a);
        const ulonglong2* e2 = reinterpret_cast<const ulonglong2*>(&s_e[nl][j * EE]);
#pragma unroll
        for (int q = 0; q < 4; q++) {
            ulonglong2 ev = e2[q];
            acc[2 * q]     = ffma2(a2, ev.x, acc[2 * q]);
            acc[2 * q + 1] = ffma2(a2, ev.y, acc[2 * q + 1]);
        }
    }

    // scale, split to bf16 hi/lo, pack, store 2x uint4 per array
    const float sc = 1.0f / (float)KK;
    uint32_t hu[8], lu[8];
#pragma unroll
    for (int q = 0; q < 8; q++) {
        float x, y;
        upk2(acc[q], x, y);
        x *= sc; y *= sc;
        uint32_t h = bfpack(y, x);                     // y upper, x lower
        float hx = __uint_as_float(h << 16);
        float hy = __uint_as_float(h & 0xffff0000u);
        hu[q] = h;
        lu[q] = bfpack(y - hy, x - hx);
    }
    size_t off = (size_t)g * SK + l * EE;
    *reinterpret_cast<uint4*>(g_Sh + off)     = make_uint4(hu[0], hu[1], hu[2], hu[3]);
    *reinterpret_cast<uint4*>(g_Sh + off + 8) = make_uint4(hu[4], hu[5], hu[6], hu[7]);
    *reinterpret_cast<uint4*>(g_Sl + off)     = make_uint4(lu[0], lu[1], lu[2], lu[3]);
    *reinterpret_cast<uint4*>(g_Sl + off + 8) = make_uint4(lu[4], lu[5], lu[6], lu[7]);
}

// ---- kernel 2: HMMA GEMM out[32768 x 64] = S @ W2 (split-bf16, 3 products) ----
// Block: 256 thr (8 warps), M-tile 128 (16 rows/warp), N = 64 (8 n-tiles),
// K chunk 64 (4 ksteps of 16). Smem padded to 72 halves/row (144 B) ->
// conflict-free ldmatrix.
#define KC 64
#define APITCH 72
#define SM_A_H 0
#define SM_A_L (128 * APITCH * 2)            // 18432
#define SM_B_H (2 * 128 * APITCH * 2)        // 36864
#define SM_B_L (SM_B_H + 64 * APITCH * 2)    // 46080
#define SMEM2_SZ (SM_B_L + 64 * APITCH * 2)  // 55296

__global__ __launch_bounds__(256) void k_stage2(float* __restrict__ out)
{
    extern __shared__ __align__(16) char sm[];
    const int t    = threadIdx.x;
    const int w    = t >> 5;
    const int lane = t & 31;
    const int m0   = blockIdx.x * 128;
    const uint32_t sb = smem_u32(sm);

    // ldmatrix lane-address decode
    const int a_r = (lane & 7) + ((lane >> 3) & 1) * 8;   // row within 16
    const int a_k = (lane >> 4) * 8;                      // k offset 0/8
    const int b_n = 8 * (lane >> 4) + (lane & 7);         // n within 16-pair
    const int b_k = 8 * ((lane >> 3) & 1);                // k offset 0/8
    const uint32_t aAh = sb + SM_A_H + (w * 16 + a_r) * 144 + a_k * 2;
    const uint32_t aAl = sb + SM_A_L + (w * 16 + a_r) * 144 + a_k * 2;
    const uint32_t aBh = sb + SM_B_H + b_n * 144 + b_k * 2;
    const uint32_t aBl = sb + SM_B_L + b_n * 144 + b_k * 2;

    // gmem load decode: A: 4 uint4/thread/half, B: 2 uint4/thread/half
    const int ar = t >> 3;          // rows t/8, +32 per q
    const int aj = t & 7;           // 16B unit within 128B row-chunk

    float acc[8][4];
#pragma unroll
    for (int nt = 0; nt < 8; nt++)
#pragma unroll
        for (int i = 0; i < 4; i++) acc[nt][i] = 0.0f;

    for (int c = 0; c < SK / KC; c++) {
        const int kk = c * KC;
        // prefetch gmem -> regs (overlaps previous chunk's MMA)
        uint4 ra_h[4], ra_l[4], rb_h[2], rb_l[2];
#pragma unroll
        for (int q = 0; q < 4; q++) {
            size_t src = (size_t)(m0 + ar + 32 * q) * SK + kk + aj * 8;
            ra_h[q] = *reinterpret_cast<const uint4*>(g_Sh + src);
            ra_l[q] = *reinterpret_cast<const uint4*>(g_Sl + src);
        }
#pragma unroll
        for (int q = 0; q < 2; q++) {
            size_t src = (size_t)(ar + 32 * q) * SK + kk + aj * 8;
            rb_h[q] = *reinterpret_cast<const uint4*>(g_Bh + src);
            rb_l[q] = *reinterpret_cast<const uint4*>(g_Bl + src);
        }
        __syncthreads();   // previous chunk's compute done before overwrite
#pragma unroll
        for (int q = 0; q < 4; q++) {
            int boff = (ar + 32 * q) * 144 + aj * 16;
            *reinterpret_cast<uint4*>(sm + SM_A_H + boff) = ra_h[q];
            *reinterpret_cast<uint4*>(sm + SM_A_L + boff) = ra_l[q];
        }
#pragma unroll
        for (int q = 0; q < 2; q++) {
            int boff = (ar + 32 * q) * 144 + aj * 16;
            *reinterpret_cast<uint4*>(sm + SM_B_H + boff) = rb_h[q];
            *reinterpret_cast<uint4*>(sm + SM_B_L + boff) = rb_l[q];
        }
        __syncthreads();

#pragma unroll
        for (int ks = 0; ks < 4; ks++) {
            const int kb2 = ks * 32;   // kstep*16 halves = *32 bytes
            uint32_t a_h[4], a_l[4];
            ldsm4(a_h, aAh + kb2);
            ldsm4(a_l, aAl + kb2);
            uint32_t bh[8][2], bl[8][2];
#pragma unroll
            for (int p = 0; p < 4; p++) {
                uint32_t r4[4];
                ldsm4(r4, aBh + p * 16 * 144 + kb2);
                bh[2 * p][0] = r4[0]; bh[2 * p][1] = r4[1];
                bh[2 * p + 1][0] = r4[2]; bh[2 * p + 1][1] = r4[3];
                ldsm4(r4, aBl + p * 16 * 144 + kb2);
                bl[2 * p][0] = r4[0]; bl[2 * p][1] = r4[1];
                bl[2 * p + 1][0] = r4[2]; bl[2 * p + 1][1] = r4[3];
            }
#pragma unroll
            for (int nt = 0; nt < 8; nt++) {
                mma16816(acc[nt], a_h, bh[nt]);
                mma16816(acc[nt], a_h, bl[nt]);
                mma16816(acc[nt], a_l, bh[nt]);
            }
        }
    }

    // epilogue: c0,c1 -> (m = t/4, n = 8nt + 2(t%4)); c2,c3 -> m+8
    const int row0 = m0 + w * 16 + (lane >> 2);
    const int cb   = 2 * (lane & 3);
#pragma unroll
    for (int nt = 0; nt < 8; nt++) {
        *reinterpret_cast<float2*>(out + (size_t)row0 * FF + 8 * nt + cb) =
            make_float2(acc[nt][0], acc[nt][1]);
        *reinterpret_cast<float2*>(out + (size_t)(row0 + 8) * FF + 8 * nt + cb) =
            make_float2(acc[nt][2], acc[nt][3]);
    }
}

extern "C" void kernel_launch(void* const* d_in, const int* in_sizes, int n_in,
                              void* d_out, int out_size) {
    const float* nodes = (const float*)d_in[0];
    const int*   nlist = (const int*)d_in[1];
    const float* edges = (const float*)d_in[2];
    const float* w     = (const float*)d_in[3];
    float* out = (float*)d_out;
    (void)in_sizes; (void)n_in; (void)out_size;

    cudaFuncSetAttribute(k_stage2,
                         cudaFuncAttributeMaxDynamicSharedMemorySize, SMEM2_SZ);

    k_w2<<<(FF * SK + 255) / 256, 256>>>(w);
    k_stage1<<<NT / 4, 256>>>(nodes, nlist, edges);
    k_stage2<<<NT / 128, 256, SMEM2_SZ>>>(out);
}